// round 13
// baseline (speedup 1.0000x reference)
#include <cuda_runtime.h>

#define FF 16
#define SS 28
#define B_ 1024
#define NBLK (B_ * 2)
#define NPROD 9

// Effective affine map: out[b,co,d,h,w] = sum_i E[co,i,fd,fh,fw]*x[b,i] + B[co,fd,fh,fw]
__device__ float g_E[3 * 3 * 5 * 5 * 5];   // 1125
__device__ float g_B[3 * 5 * 5 * 5];       // 375
__device__ int          g_prod_cnt = 0;    // producers finished (0..9)
__device__ unsigned int g_done_cnt = 0;    // blocks finished (for replay reset)

__device__ __forceinline__ int fcls(int p, int n) {
    int c = 2;
    if (p == 0)          c = 0;
    else if (p == 1)     c = 1;
    else if (p == n - 1) c = 4;
    else if (p == n - 2) c = 3;
    return c;
}

// conv1 3-class mask: class 0 drops tap k=0, class 2 drops tap k=2.
__device__ __forceinline__ float mask3(int c, int k) {
    return ((c == 0 && k == 0) || (c == 2 && k == 2)) ? 0.f : 1.f;
}

// ---------------------------------------------------------------------------
// SINGLE fused kernel, grid 2048 x 224.
//  * Blocks 0-8 ("leaders") compute the E/B table slices (same math as the
//    old 9-block precompute kernel), release-fence, and bump g_prod_cnt.
//  * Every block spins (lane 0 only, nanosleep backoff) until g_prod_cnt==9
//    — a ONE-TIME ~1.5us grid-wide stall, not a per-block rebuild (R7's
//    mistake) and not a 6us kernel-boundary (R6-R12's tax).
//  * Then the exact R8 expand body (measured 26.5us = DRAM write floor).
//  * Last finishing block resets both counters -> every replay identical.
// ---------------------------------------------------------------------------
__global__ void __launch_bounds__(224) fused_kernel(
        const float* __restrict__ x,
        const float* __restrict__ w1, const float* __restrict__ b1,
        const float* __restrict__ w2, const float* __restrict__ b2,
        float4* __restrict__ out) {
    __shared__ float v[375];           // v[co*125 + fd*25 + fh*5 + fw]
    const int blk = blockIdx.x;
    const int b   = blk >> 1;
    const int p   = blk & 1;           // d-half: 0 -> d 0..7, 1 -> d 8..15
    const int tid = threadIdx.x;

    // x loads are independent of the tables — issue before any waiting.
    float x0 = __ldg(&x[b * 3 + 0]);
    float x1 = __ldg(&x[b * 3 + 1]);
    float x2 = __ldg(&x[b * 3 + 2]);

    // ---------------- producer: table slice (blocks 0-8) ----------------
    if (blk < NPROD) {
        __shared__ float sw1[324], sw2[324], S1[324];
        __shared__ float sb1[4], sb2[3];

        for (int e = tid; e < 324; e += 224) { sw1[e] = w1[e]; sw2[e] = w2[e]; }
        if (tid < 4) sb1[tid] = b1[tid];
        if (tid < 3) sb2[tid] = b2[tid];
        __syncthreads();

        // S1[o][i][cd*9+ch*3+cw]: branch-free masked tap-sums of w1.
        for (int e = tid; e < 324; e += 224) {
            int cw = e % 3, ch = (e / 3) % 3, cd = (e / 9) % 3;
            int base = (e / 27) * 27;
            float s = 0.f;
#pragma unroll
            for (int kd = 0; kd < 3; kd++) {
                float md = mask3(cd, kd);
#pragma unroll
                for (int kh = 0; kh < 3; kh++) {
                    float mh = md * mask3(ch, kh);
#pragma unroll
                    for (int kw = 0; kw < 3; kw++)
                        s += mh * mask3(cw, kw) * sw1[base + kd * 9 + kh * 3 + kw];
                }
            }
            S1[e] = s;
        }
        __syncthreads();

        if (tid < 125) {
            const int fw = tid % 5, fh = (tid / 5) % 5, fd = tid / 25;

            float vaD[3], vaH[3], vaW[3];
            int   nbD[3], nbH[3], nbW[3];
#pragma unroll
            for (int tt = 0; tt < 3; tt++) {
                vaD[tt] = ((fd == 0 && tt == 0) || (fd == 4 && tt == 2)) ? 0.f : 1.f;
                vaH[tt] = ((fh == 0 && tt == 0) || (fh == 4 && tt == 2)) ? 0.f : 1.f;
                vaW[tt] = ((fw == 0 && tt == 0) || (fw == 4 && tt == 2)) ? 0.f : 1.f;
                int pd = fd + tt - 1; nbD[tt] = (pd == 0) ? 0 : (pd == 4) ? 2 : 1;
                int ph = fh + tt - 1; nbH[tt] = (ph == 0) ? 0 : (ph == 4) ? 2 : 1;
                int pw = fw + tt - 1; nbW[tt] = (pw == 0) ? 0 : (pw == 4) ? 2 : 1;
            }

            {   // E slice: element blk*125 + tid;  i = blk%3, co = blk/3.
                const int i  = blk % 3;
                const int co = blk / 3;
                float a0 = 0.f, a1 = 0.f, a2 = 0.f, a3 = 0.f;
#pragma unroll
                for (int td = 0; td < 3; td++) {
                    float cD = vaD[td]; int cd9 = nbD[td] * 9;
#pragma unroll
                    for (int th = 0; th < 3; th++) {
                        float cH = cD * vaH[th]; int ch3 = cd9 + nbH[th] * 3;
#pragma unroll
                        for (int tw = 0; tw < 3; tw++) {
                            float coef = cH * vaW[tw];
                            int w2i = co * 108 + td * 9 + th * 3 + tw;   // + o*27
                            int s1i = i * 27 + ch3 + nbW[tw];            // + o*81
                            a0 += coef * sw2[w2i      ] * S1[s1i      ];
                            a1 += coef * sw2[w2i +  27] * S1[s1i +  81];
                            a2 += coef * sw2[w2i +  54] * S1[s1i + 162];
                            a3 += coef * sw2[w2i +  81] * S1[s1i + 243];
                        }
                    }
                }
                g_E[blk * 125 + tid] = (a0 + a1) + (a2 + a3);
            }

            if (blk < 3) {   // B: blocks 0-2 own co = blk.
                const int co = blk;
                float s = sb2[co];
#pragma unroll
                for (int o = 0; o < 4; o++) {
                    float ws = 0.f;
#pragma unroll
                    for (int td = 0; td < 3; td++) {
#pragma unroll
                        for (int th = 0; th < 3; th++) {
                            float cH = vaD[td] * vaH[th];
#pragma unroll
                            for (int tw = 0; tw < 3; tw++)
                                ws += cH * vaW[tw] * sw2[co * 108 + o * 27 + td * 9 + th * 3 + tw];
                        }
                    }
                    s += sb1[o] * ws;
                }
                g_B[blk * 125 + tid] = s;
            }
        }

        // Release: every thread fences its stores, then one thread signals.
        __threadfence();
        __syncthreads();
        if (tid == 0) atomicAdd(&g_prod_cnt, 1);
    }

    // ---------------- consumer: wait until all 9 slices published --------
    if (tid == 0) {
        while (*(volatile int*)&g_prod_cnt < NPROD) __nanosleep(200);
    }
    __syncthreads();
    __threadfence();   // order table reads after the flag observation

    // ---------------- expand (exact R8 26.5us body) ----------------------
    for (int e = tid; e < 375; e += 224) {
        int co = e / 125;
        int sp = e - co * 125;
        int eb = co * 375 + sp;        // i stride = 125 in g_E
        v[e] = g_B[e] + x0 * g_E[eb] + x1 * g_E[eb + 125] + x2 * g_E[eb + 250];
    }
    __syncthreads();

    if (tid < 196) {
        int h  = tid / 7;
        int w4 = tid - h * 7;
        int fh = fcls(h, SS);
        int i0 = (w4 == 0) ? 0 : 2;
        int i1 = (w4 == 0) ? 1 : 2;
        int i2 = (w4 == 6) ? 3 : 2;
        int i3 = (w4 == 6) ? 4 : 2;
        int base = fh * 5;

        const int dcls0[8] = {0,1,2,2,2,2,2,2};
        const int dcls1[8] = {2,2,2,2,2,2,3,4};

        float4* op = out + (size_t)b * (3 * FF * 196) + (size_t)p * (8 * 196) + tid;
#pragma unroll
        for (int co = 0; co < 3; co++) {
#pragma unroll
            for (int dd = 0; dd < 8; dd++) {
                int fd = p ? dcls1[dd] : dcls0[dd];
                const float* vv = v + co * 125 + fd * 25 + base;
                float4 o4 = make_float4(vv[i0], vv[i1], vv[i2], vv[i3]);
                op[(co * FF + dd) * 196] = o4;
            }
        }
    }

    // ---------------- replay reset: last block restores counters ---------
    __syncthreads();
    if (tid == 0) {
        unsigned int done = atomicAdd(&g_done_cnt, 1);
        if (done == NBLK - 1) {
            g_prod_cnt = 0;
            g_done_cnt = 0;
            __threadfence();
        }
    }
}

extern "C" void kernel_launch(void* const* d_in, const int* in_sizes, int n_in,
                              void* d_out, int out_size) {
    const float* x  = (const float*)d_in[0];
    const float* w1 = (const float*)d_in[1];
    const float* b1 = (const float*)d_in[2];
    const float* w2 = (const float*)d_in[3];
    const float* b2 = (const float*)d_in[4];

    fused_kernel<<<NBLK, 224>>>(x, w1, b1, w2, b2, (float4*)d_out);
}